// round 3
// baseline (speedup 1.0000x reference)
#include <cuda_runtime.h>
#include <cuda_bf16.h>
#include <cstdint>
#include <math.h>

// ---------------- problem constants ----------------
#define BDIM   4096          // batch rows
#define KDIM   4096          // F + S
#define NGATE  6144          // 3*S
#define SDIM   2048
#define HSIZE  8388608L      // B*S

// ---------------- GEMM tile config (bf16 mma.sync m16n8k16, 3-product split) ----------------
#define BM 256
#define BN 128
#define BK 32                // 32 bf16 along k per chunk = 2 k16 slices
#define KT (KDIM / BK)       // 128 chunks per product phase
#define NPHASE 3             // A0B0 + A1B0 + A0B1
#define TOT_ITERS (NPHASE * KT)   // 384
#define STAGES 4

// smem word-layout (32-bit words, 2 bf16 per word), padded stride for conflict-free LDS
#define AW 20                // words per A row (16 data + 4 pad) -> stride 20g+t4 conflict-free
#define BW 20                // words per B row
#define A_WORDS (BM * AW)            // 5120
#define B_WORDS (BN * BW)            // 2560
#define STAGE_WORDS (A_WORDS + B_WORDS)   // 7680
#define STAGE_BYTES (STAGE_WORDS * 4)     // 30720
#define SMEM_TOTAL (STAGES * STAGE_BYTES) // 122880

// ---------------- scratch (no cudaMalloc allowed) ----------------
__device__ __nv_bfloat16 g_A0[(long)BDIM * KDIM];    // 32MB  bf16(X)
__device__ __nv_bfloat16 g_A1[(long)BDIM * KDIM];    // 32MB  bf16(X - A0)
__device__ __nv_bfloat16 g_B0[(long)NGATE * KDIM];   // 50MB  bf16(W^T)
__device__ __nv_bfloat16 g_B1[(long)NGATE * KDIM];   // 50MB  bf16(W^T - B0)
__device__ float g_G[(long)BDIM * NGATE];            // 96MB  raw gate pre-activations

// ---------------- helpers ----------------
__device__ __forceinline__ uint32_t smem_u32(const void* p) {
    uint32_t a;
    asm("{ .reg .u64 t; cvta.to.shared.u64 t, %1; cvt.u32.u64 %0, t; }" : "=r"(a) : "l"(p));
    return a;
}
__device__ __forceinline__ void cp16(uint32_t dst, const void* src) {
    asm volatile("cp.async.cg.shared.global [%0], [%1], 16;" :: "r"(dst), "l"(src) : "memory");
}
__device__ __forceinline__ void cp_commit() {
    asm volatile("cp.async.commit_group;" ::: "memory");
}
template <int N>
__device__ __forceinline__ void cp_wait() {
    asm volatile("cp.async.wait_group %0;" :: "n"(N) : "memory");
}
__device__ __forceinline__ void mma_bf16(float* c, const uint32_t* a, const uint32_t* b) {
    asm volatile(
        "mma.sync.aligned.m16n8k16.row.col.f32.bf16.bf16.f32 "
        "{%0,%1,%2,%3}, {%4,%5,%6,%7}, {%8,%9}, {%0,%1,%2,%3};"
        : "+f"(c[0]), "+f"(c[1]), "+f"(c[2]), "+f"(c[3])
        : "r"(a[0]), "r"(a[1]), "r"(a[2]), "r"(a[3]), "r"(b[0]), "r"(b[1]));
}
__device__ __forceinline__ void split2(float x, __nv_bfloat16& h0, __nv_bfloat16& h1) {
    h0 = __float2bfloat16_rn(x);
    h1 = __float2bfloat16_rn(x - __bfloat162float(h0));
}

// ---------------- prologue: pack & split X = [old_h | input] ----------------
__global__ void pack_split_x(const float* __restrict__ old_h, const float* __restrict__ input,
                             __nv_bfloat16* __restrict__ A0, __nv_bfloat16* __restrict__ A1) {
    long i = (long)blockIdx.x * blockDim.x + threadIdx.x;   // float4 units, 4096*1024
    int m = (int)(i >> 10);
    int kq = (int)(i & 1023);
    float4 v = (kq < 512) ? reinterpret_cast<const float4*>(old_h)[(long)m * 512 + kq]
                          : reinterpret_cast<const float4*>(input)[(long)m * 512 + (kq - 512)];
    __nv_bfloat16 h0[4], h1[4];
    split2(v.x, h0[0], h1[0]);
    split2(v.y, h0[1], h1[1]);
    split2(v.z, h0[2], h1[2]);
    split2(v.w, h0[3], h1[3]);
    *reinterpret_cast<uint2*>(&A0[4 * i]) = *reinterpret_cast<uint2*>(h0);
    *reinterpret_cast<uint2*>(&A1[4 * i]) = *reinterpret_cast<uint2*>(h1);
}

// ---------------- prologue: transpose & split W -> Wt[n][k] ----------------
__global__ void split_w_kernel(const float* __restrict__ W,
                               __nv_bfloat16* __restrict__ B0, __nv_bfloat16* __restrict__ B1) {
    __shared__ float tile[32][33];
    int n0 = blockIdx.x * 32, k0 = blockIdx.y * 32;
    int tx = threadIdx.x, ty = threadIdx.y;
#pragma unroll
    for (int i = 0; i < 32; i += 8)
        tile[ty + i][tx] = W[(long)(k0 + ty + i) * NGATE + n0 + tx];
    __syncthreads();
#pragma unroll
    for (int i = 0; i < 32; i += 8) {
        long n = n0 + ty + i, k = k0 + tx;
        __nv_bfloat16 h0, h1;
        split2(tile[tx][ty + i], h0, h1);
        B0[n * KDIM + k] = h0;
        B1[n * KDIM + k] = h1;
    }
}

// ---------------- main GEMM: G = sum of 3 bf16 products (K tripled) ----------------
// CTA 256x128, 8 warps 4(m)x2(n), warp tile 64x64 (4 mtiles x 8 ntiles of m16n8).
__global__ void __launch_bounds__(256, 1) gemm_kernel(
    const __nv_bfloat16* __restrict__ A0, const __nv_bfloat16* __restrict__ A1,
    const __nv_bfloat16* __restrict__ B0, const __nv_bfloat16* __restrict__ B1,
    float* __restrict__ G) {
    extern __shared__ uint32_t smw[];
    const uint32_t sbase = smem_u32(smw);

    const int tid = threadIdx.x;
    const int warp = tid >> 5, lane = tid & 31;
    const int wm = warp >> 1, wn = warp & 1;
    const int g = lane >> 2, t4 = lane & 3;
    const long m0 = (long)blockIdx.x * BM;
    const long n0 = (long)blockIdx.y * BN;

    float acc[4][8][4];
#pragma unroll
    for (int i = 0; i < 4; i++)
#pragma unroll
        for (int j = 0; j < 8; j++)
#pragma unroll
            for (int r = 0; r < 4; r++) acc[i][j][r] = 0.0f;

    // stage loader: A 256 rows x 64B (4 chunks/row), B 128 rows x 64B
    auto issue_stage = [&](int t) {
        int slot = t & (STAGES - 1);
        int phase = t >> 7;               // t / KT
        long kk = (long)(t & (KT - 1)) * BK;
        const __nv_bfloat16* pA = (phase == 1) ? A1 : A0;
        const __nv_bfloat16* pB = (phase == 2) ? B1 : B0;
        uint32_t sA = sbase + slot * STAGE_BYTES;
        uint32_t sB = sA + A_WORDS * 4;
#pragma unroll
        for (int i = 0; i < 4; i++) {
            int q = tid + i * 256;
            int row = q >> 2, cw = q & 3;
            cp16(sA + row * (AW * 4) + cw * 16, pA + (m0 + row) * KDIM + kk + cw * 8);
        }
#pragma unroll
        for (int i = 0; i < 2; i++) {
            int q = tid + i * 256;
            int row = q >> 2, cw = q & 3;
            cp16(sB + row * (BW * 4) + cw * 16, pB + (n0 + row) * KDIM + kk + cw * 8);
        }
    };

#pragma unroll
    for (int s = 0; s < STAGES - 1; s++) {
        issue_stage(s);
        cp_commit();
    }

    const int arow = wm * 64 + g;
    const int bnrow = wn * 64 + g;

    for (int t = 0; t < TOT_ITERS; t++) {
        cp_wait<STAGES - 2>();
        __syncthreads();

        if (t + STAGES - 1 < TOT_ITERS) issue_stage(t + STAGES - 1);
        cp_commit();

        const uint32_t* As = smw + (t & (STAGES - 1)) * STAGE_WORDS;
        const uint32_t* Bs = As + A_WORDS;

#pragma unroll
        for (int s = 0; s < 2; s++) {
            const int kw = 8 * s + t4;
            uint32_t a[4][4];
#pragma unroll
            for (int i = 0; i < 4; i++) {
                const uint32_t* ap = As + (arow + i * 16) * AW + kw;
                a[i][0] = ap[0];
                a[i][1] = ap[8 * AW];
                a[i][2] = ap[4];
                a[i][3] = ap[8 * AW + 4];
            }
            uint32_t b[8][2];
#pragma unroll
            for (int j = 0; j < 8; j++) {
                const uint32_t* bp = Bs + (bnrow + j * 8) * BW + kw;
                b[j][0] = bp[0];
                b[j][1] = bp[4];
            }
#pragma unroll
            for (int i = 0; i < 4; i++)
#pragma unroll
                for (int j = 0; j < 8; j++) mma_bf16(acc[i][j], a[i], b[j]);
        }
    }

    // store raw gates (fp32)
#pragma unroll
    for (int i = 0; i < 4; i++) {
        long row0 = m0 + wm * 64 + i * 16 + g;
#pragma unroll
        for (int j = 0; j < 8; j++) {
            long col = n0 + wn * 64 + j * 8 + 2 * t4;
            *reinterpret_cast<float2*>(&G[row0 * NGATE + col]) =
                make_float2(acc[i][j][0], acc[i][j][1]);
            *reinterpret_cast<float2*>(&G[(row0 + 8) * NGATE + col]) =
                make_float2(acc[i][j][2], acc[i][j][3]);
        }
    }
}

// ---------------- fused pointwise epilogue ----------------
__global__ void epilogue_kernel(const float* __restrict__ G, const float* __restrict__ bias,
                                const float* __restrict__ old_c, float* __restrict__ out) {
    long i = (long)blockIdx.x * blockDim.x + threadIdx.x;   // float4 units, 4096*512
    int m = (int)(i >> 9);
    int sq = (int)(i & 511);

    const float4* G4 = reinterpret_cast<const float4*>(G);
    const float4* B4 = reinterpret_cast<const float4*>(bias);
    float4 gi = G4[(long)m * 1536 + sq];
    float4 go = G4[(long)m * 1536 + 512 + sq];
    float4 gc = G4[(long)m * 1536 + 1024 + sq];
    float4 bi = B4[sq];
    float4 bo = B4[512 + sq];
    float4 bc = B4[1024 + sq];
    float4 oc = reinterpret_cast<const float4*>(old_c)[i];

    float4 nh, nc;
    {
        float vi, vo, vc, ig, og, cc, cell;
#define LANE(f)                                                     \
        vi = gi.f + bi.f; vo = go.f + bo.f; vc = gc.f + bc.f;       \
        ig = 1.0f / (1.0f + expf(-vi));                             \
        og = 1.0f / (1.0f + expf(-vo));                             \
        cc = (vc > 0.0f) ? vc : expm1f(vc);                         \
        cell = oc.f + cc * ig;                                      \
        nc.f = cell;                                                \
        nh.f = tanhf(cell) * og;
        LANE(x) LANE(y) LANE(z) LANE(w)
#undef LANE
    }
    reinterpret_cast<float4*>(out)[i] = nh;
    reinterpret_cast<float4*>(out)[HSIZE / 4 + i] = nc;
}

// ---------------- host ----------------
extern "C" void kernel_launch(void* const* d_in, const int* in_sizes, int n_in,
                              void* d_out, int out_size) {
    const float* W     = (const float*)d_in[0];   // (4096, 6144)
    const float* bias  = (const float*)d_in[1];   // (6144,)
    const float* input = (const float*)d_in[2];   // (4096, 2048)
    const float* old_h = (const float*)d_in[3];   // (4096, 2048)
    const float* old_c = (const float*)d_in[4];   // (4096, 2048)
    float* out = (float*)d_out;                   // [new_h | new_cell]

    void *pA0, *pA1, *pB0, *pB1, *pG;
    cudaGetSymbolAddress(&pA0, g_A0);
    cudaGetSymbolAddress(&pA1, g_A1);
    cudaGetSymbolAddress(&pB0, g_B0);
    cudaGetSymbolAddress(&pB1, g_B1);
    cudaGetSymbolAddress(&pG, g_G);

    pack_split_x<<<16384, 256>>>(old_h, input, (__nv_bfloat16*)pA0, (__nv_bfloat16*)pA1);
    split_w_kernel<<<dim3(NGATE / 32, KDIM / 32), dim3(32, 8)>>>(
        W, (__nv_bfloat16*)pB0, (__nv_bfloat16*)pB1);

    cudaFuncSetAttribute(gemm_kernel, cudaFuncAttributeMaxDynamicSharedMemorySize, SMEM_TOTAL);
    gemm_kernel<<<dim3(BDIM / BM, NGATE / BN), 256, SMEM_TOTAL>>>(
        (const __nv_bfloat16*)pA0, (const __nv_bfloat16*)pA1,
        (const __nv_bfloat16*)pB0, (const __nv_bfloat16*)pB1, (float*)pG);

    epilogue_kernel<<<8192, 256>>>((const float*)pG, bias, old_c, out);
}

// round 4
// speedup vs baseline: 1.1853x; 1.1853x over previous
#include <cuda_runtime.h>
#include <cuda_bf16.h>
#include <cstdint>
#include <math.h>

// ---------------- problem constants ----------------
#define BDIM   4096          // batch rows
#define KDIM   4096          // F + S
#define NGATE  6144          // 3*S
#define SDIM   2048
#define HSIZE  8388608L      // B*S

// ---------------- GEMM tile config (bf16 mma.sync m16n8k16, 3-product split) ----------------
#define BM 256
#define BN 128
#define BK 64                // 64 bf16 along k per chunk = 4 k16 slices
#define KT (KDIM / BK)       // 64 chunks per product phase
#define NPHASE 3             // A0B0 + A1B0 + A0B1
#define TOT_ITERS (NPHASE * KT)   // 192
#define STAGES 3

// smem layout: row stride 144 bytes (128 data + 16 pad) -> conflict-free ldmatrix + cp.async
#define ROWB 144
#define A_BYTES (BM * ROWB)          // 36864
#define B_BYTES (BN * ROWB)          // 18432
#define STAGE_BYTES (A_BYTES + B_BYTES)   // 55296
#define SMEM_TOTAL (STAGES * STAGE_BYTES) // 165888

// ---------------- scratch (no cudaMalloc allowed) ----------------
__device__ __nv_bfloat16 g_A0[(long)BDIM * KDIM];    // 32MB  bf16(X)
__device__ __nv_bfloat16 g_A1[(long)BDIM * KDIM];    // 32MB  bf16(X - A0)
__device__ __nv_bfloat16 g_B0[(long)NGATE * KDIM];   // 50MB  bf16(W^T)
__device__ __nv_bfloat16 g_B1[(long)NGATE * KDIM];   // 50MB  bf16(W^T - B0)
__device__ float g_G[(long)BDIM * NGATE];            // 96MB  raw gate pre-activations

// ---------------- helpers ----------------
__device__ __forceinline__ uint32_t smem_u32(const void* p) {
    uint32_t a;
    asm("{ .reg .u64 t; cvta.to.shared.u64 t, %1; cvt.u32.u64 %0, t; }" : "=r"(a) : "l"(p));
    return a;
}
__device__ __forceinline__ void cp16(uint32_t dst, const void* src) {
    asm volatile("cp.async.cg.shared.global [%0], [%1], 16;" :: "r"(dst), "l"(src) : "memory");
}
__device__ __forceinline__ void cp_commit() {
    asm volatile("cp.async.commit_group;" ::: "memory");
}
template <int N>
__device__ __forceinline__ void cp_wait() {
    asm volatile("cp.async.wait_group %0;" :: "n"(N) : "memory");
}
__device__ __forceinline__ void ldsm4(uint32_t& r0, uint32_t& r1, uint32_t& r2, uint32_t& r3,
                                      uint32_t addr) {
    asm volatile("ldmatrix.sync.aligned.m8n8.x4.shared.b16 {%0,%1,%2,%3}, [%4];"
                 : "=r"(r0), "=r"(r1), "=r"(r2), "=r"(r3) : "r"(addr));
}
__device__ __forceinline__ void mma_bf16(float* c, const uint32_t* a, const uint32_t* b) {
    asm volatile(
        "mma.sync.aligned.m16n8k16.row.col.f32.bf16.bf16.f32 "
        "{%0,%1,%2,%3}, {%4,%5,%6,%7}, {%8,%9}, {%0,%1,%2,%3};"
        : "+f"(c[0]), "+f"(c[1]), "+f"(c[2]), "+f"(c[3])
        : "r"(a[0]), "r"(a[1]), "r"(a[2]), "r"(a[3]), "r"(b[0]), "r"(b[1]));
}
__device__ __forceinline__ void split2(float x, __nv_bfloat16& h0, __nv_bfloat16& h1) {
    h0 = __float2bfloat16_rn(x);
    h1 = __float2bfloat16_rn(x - __bfloat162float(h0));
}

// ---------------- prologue: pack & split X = [old_h | input] ----------------
__global__ void pack_split_x(const float* __restrict__ old_h, const float* __restrict__ input,
                             __nv_bfloat16* __restrict__ A0, __nv_bfloat16* __restrict__ A1) {
    long i = (long)blockIdx.x * blockDim.x + threadIdx.x;   // float4 units, 4096*1024
    int m = (int)(i >> 10);
    int kq = (int)(i & 1023);
    float4 v = (kq < 512) ? reinterpret_cast<const float4*>(old_h)[(long)m * 512 + kq]
                          : reinterpret_cast<const float4*>(input)[(long)m * 512 + (kq - 512)];
    __nv_bfloat16 h0[4], h1[4];
    split2(v.x, h0[0], h1[0]);
    split2(v.y, h0[1], h1[1]);
    split2(v.z, h0[2], h1[2]);
    split2(v.w, h0[3], h1[3]);
    *reinterpret_cast<uint2*>(&A0[4 * i]) = *reinterpret_cast<uint2*>(h0);
    *reinterpret_cast<uint2*>(&A1[4 * i]) = *reinterpret_cast<uint2*>(h1);
}

// ---------------- prologue: transpose & split W -> Wt[n][k] ----------------
__global__ void split_w_kernel(const float* __restrict__ W,
                               __nv_bfloat16* __restrict__ B0, __nv_bfloat16* __restrict__ B1) {
    __shared__ float tile[32][33];
    int n0 = blockIdx.x * 32, k0 = blockIdx.y * 32;
    int tx = threadIdx.x, ty = threadIdx.y;
#pragma unroll
    for (int i = 0; i < 32; i += 8)
        tile[ty + i][tx] = W[(long)(k0 + ty + i) * NGATE + n0 + tx];
    __syncthreads();
#pragma unroll
    for (int i = 0; i < 32; i += 8) {
        long n = n0 + ty + i, k = k0 + tx;
        __nv_bfloat16 h0, h1;
        split2(tile[tx][ty + i], h0, h1);
        B0[n * KDIM + k] = h0;
        B1[n * KDIM + k] = h1;
    }
}

// ---------------- main GEMM: G = sum of 3 bf16 products (K tripled) ----------------
// CTA 256x128, 8 warps 4(m)x2(n), warp tile 64x64 (4 mtiles x 8 ntiles of m16n8).
__global__ void __launch_bounds__(256, 1) gemm_kernel(
    const __nv_bfloat16* __restrict__ A0, const __nv_bfloat16* __restrict__ A1,
    const __nv_bfloat16* __restrict__ B0, const __nv_bfloat16* __restrict__ B1,
    float* __restrict__ G) {
    extern __shared__ char smem[];
    const uint32_t sbase = smem_u32(smem);

    const int tid = threadIdx.x;
    const int warp = tid >> 5, lane = tid & 31;
    const int wm = warp >> 1, wn = warp & 1;
    const int g = lane >> 2, t4 = lane & 3;
    const long m0 = (long)blockIdx.x * BM;
    const long n0 = (long)blockIdx.y * BN;

    float acc[4][8][4];
#pragma unroll
    for (int i = 0; i < 4; i++)
#pragma unroll
        for (int j = 0; j < 8; j++)
#pragma unroll
            for (int r = 0; r < 4; r++) acc[i][j][r] = 0.0f;

    // per-lane ldmatrix address offsets (within a stage)
    // A fragment (16x16): row = lane&15 within mtile, col halves selected by lane>>4
    const uint32_t a_off = (uint32_t)(wm * 64 + (lane & 15)) * ROWB + ((lane >> 4) << 4);
    // B fragment pair (16 n-rows x 16 k): n row = (lane&7) + ((lane>>4)<<3), col = (lane>>3)&1
    const uint32_t b_off =
        (uint32_t)(wn * 64 + (lane & 7) + ((lane >> 4) << 3)) * ROWB + (((lane >> 3) & 1) << 4);

    // stage loader: A 256 rows x 128B (8 chunks/row), B 128 rows x 128B
    auto issue_stage = [&](int t) {
        int slot = t % STAGES;
        int phase = t >> 6;               // t / KT
        long kk = (long)(t & (KT - 1)) * BK;
        const __nv_bfloat16* pA = (phase == 1) ? A1 : A0;
        const __nv_bfloat16* pB = (phase == 2) ? B1 : B0;
        uint32_t sA = sbase + slot * STAGE_BYTES;
        uint32_t sB = sA + A_BYTES;
#pragma unroll
        for (int i = 0; i < 8; i++) {
            int q = tid + i * 256;
            int row = q >> 3, cw = q & 7;
            cp16(sA + row * ROWB + cw * 16, pA + (m0 + row) * KDIM + kk + cw * 8);
        }
#pragma unroll
        for (int i = 0; i < 4; i++) {
            int q = tid + i * 256;
            int row = q >> 3, cw = q & 7;
            cp16(sB + row * ROWB + cw * 16, pB + (n0 + row) * KDIM + kk + cw * 8);
        }
    };

#pragma unroll
    for (int s = 0; s < STAGES - 1; s++) {
        issue_stage(s);
        cp_commit();
    }

    for (int t = 0; t < TOT_ITERS; t++) {
        cp_wait<STAGES - 2>();
        __syncthreads();

        if (t + STAGES - 1 < TOT_ITERS) issue_stage(t + STAGES - 1);
        cp_commit();

        uint32_t sA = sbase + (t % STAGES) * STAGE_BYTES;
        uint32_t sB = sA + A_BYTES;

#pragma unroll
        for (int s = 0; s < 4; s++) {           // 4 k16 slices per 64-wide chunk
            uint32_t a[4][4];
#pragma unroll
            for (int i = 0; i < 4; i++)
                ldsm4(a[i][0], a[i][1], a[i][2], a[i][3],
                      sA + a_off + (uint32_t)i * (16 * ROWB) + (uint32_t)s * 32);
            uint32_t b[8][2];
#pragma unroll
            for (int jj = 0; jj < 4; jj++)
                ldsm4(b[2 * jj][0], b[2 * jj][1], b[2 * jj + 1][0], b[2 * jj + 1][1],
                      sB + b_off + (uint32_t)jj * (16 * ROWB) + (uint32_t)s * 32);
#pragma unroll
            for (int i = 0; i < 4; i++)
#pragma unroll
                for (int j = 0; j < 8; j++) mma_bf16(acc[i][j], a[i], b[j]);
        }
    }

    // store raw gates (fp32)
#pragma unroll
    for (int i = 0; i < 4; i++) {
        long row0 = m0 + wm * 64 + i * 16 + g;
#pragma unroll
        for (int j = 0; j < 8; j++) {
            long col = n0 + wn * 64 + j * 8 + 2 * t4;
            *reinterpret_cast<float2*>(&G[row0 * NGATE + col]) =
                make_float2(acc[i][j][0], acc[i][j][1]);
            *reinterpret_cast<float2*>(&G[(row0 + 8) * NGATE + col]) =
                make_float2(acc[i][j][2], acc[i][j][3]);
        }
    }
}

// ---------------- fused pointwise epilogue ----------------
__global__ void epilogue_kernel(const float* __restrict__ G, const float* __restrict__ bias,
                                const float* __restrict__ old_c, float* __restrict__ out) {
    long i = (long)blockIdx.x * blockDim.x + threadIdx.x;   // float4 units, 4096*512
    int m = (int)(i >> 9);
    int sq = (int)(i & 511);

    const float4* G4 = reinterpret_cast<const float4*>(G);
    const float4* B4 = reinterpret_cast<const float4*>(bias);
    float4 gi = G4[(long)m * 1536 + sq];
    float4 go = G4[(long)m * 1536 + 512 + sq];
    float4 gc = G4[(long)m * 1536 + 1024 + sq];
    float4 bi = B4[sq];
    float4 bo = B4[512 + sq];
    float4 bc = B4[1024 + sq];
    float4 oc = reinterpret_cast<const float4*>(old_c)[i];

    float4 nh, nc;
    {
        float vi, vo, vc, ig, og, cc, cell;
#define LANE(f)                                                     \
        vi = gi.f + bi.f; vo = go.f + bo.f; vc = gc.f + bc.f;       \
        ig = 1.0f / (1.0f + expf(-vi));                             \
        og = 1.0f / (1.0f + expf(-vo));                             \
        cc = (vc > 0.0f) ? vc : expm1f(vc);                         \
        cell = oc.f + cc * ig;                                      \
        nc.f = cell;                                                \
        nh.f = tanhf(cell) * og;
        LANE(x) LANE(y) LANE(z) LANE(w)
#undef LANE
    }
    reinterpret_cast<float4*>(out)[i] = nh;
    reinterpret_cast<float4*>(out)[HSIZE / 4 + i] = nc;
}

// ---------------- host ----------------
extern "C" void kernel_launch(void* const* d_in, const int* in_sizes, int n_in,
                              void* d_out, int out_size) {
    const float* W     = (const float*)d_in[0];   // (4096, 6144)
    const float* bias  = (const float*)d_in[1];   // (6144,)
    const float* input = (const float*)d_in[2];   // (4096, 2048)
    const float* old_h = (const float*)d_in[3];   // (4096, 2048)
    const float* old_c = (const float*)d_in[4];   // (4096, 2048)
    float* out = (float*)d_out;                   // [new_h | new_cell]

    void *pA0, *pA1, *pB0, *pB1, *pG;
    cudaGetSymbolAddress(&pA0, g_A0);
    cudaGetSymbolAddress(&pA1, g_A1);
    cudaGetSymbolAddress(&pB0, g_B0);
    cudaGetSymbolAddress(&pB1, g_B1);
    cudaGetSymbolAddress(&pG, g_G);

    pack_split_x<<<16384, 256>>>(old_h, input, (__nv_bfloat16*)pA0, (__nv_bfloat16*)pA1);
    split_w_kernel<<<dim3(NGATE / 32, KDIM / 32), dim3(32, 8)>>>(
        W, (__nv_bfloat16*)pB0, (__nv_bfloat16*)pB1);

    cudaFuncSetAttribute(gemm_kernel, cudaFuncAttributeMaxDynamicSharedMemorySize, SMEM_TOTAL);
    gemm_kernel<<<dim3(BDIM / BM, NGATE / BN), 256, SMEM_TOTAL>>>(
        (const __nv_bfloat16*)pA0, (const __nv_bfloat16*)pA1,
        (const __nv_bfloat16*)pB0, (const __nv_bfloat16*)pB1, (float*)pG);

    epilogue_kernel<<<8192, 256>>>((const float*)pG, bias, old_c, out);
}

// round 5
// speedup vs baseline: 1.2389x; 1.0452x over previous
#include <cuda_runtime.h>
#include <cuda_bf16.h>
#include <cstdint>
#include <math.h>

// ---------------- problem constants ----------------
#define BDIM   4096          // batch rows
#define KDIM   4096          // F + S
#define NGATE  6144          // 3*S
#define SDIM   2048
#define HSIZE  8388608L      // B*S

// ---------------- GEMM tile config (bf16 mma.sync m16n8k16, 3-product split) ----------------
#define BM 256
#define BN 96                // 16 x 64 = 1024 CTAs -> 6.92 waves on 148 SMs (1.2% tail)
#define BK 64                // 64 bf16 along k per chunk = 4 k16 slices
#define KT (KDIM / BK)       // 64 chunks per product phase
#define NPHASE 3             // A0B0 + A1B0 + A0B1
#define TOT_ITERS (NPHASE * KT)   // 192
#define STAGES 3

// smem layout: row stride 144 bytes (128 data + 16 pad) -> conflict-free ldmatrix + cp.async
#define ROWB 144
#define A_BYTES (BM * ROWB)          // 36864
#define B_BYTES (BN * ROWB)          // 13824
#define STAGE_BYTES (A_BYTES + B_BYTES)   // 50688
#define SMEM_TOTAL (STAGES * STAGE_BYTES) // 152064

// ---------------- scratch (no cudaMalloc allowed) ----------------
__device__ __nv_bfloat16 g_A0[(long)BDIM * KDIM];    // 32MB  bf16(X)
__device__ __nv_bfloat16 g_A1[(long)BDIM * KDIM];    // 32MB  bf16(X - A0)
__device__ __nv_bfloat16 g_B0[(long)NGATE * KDIM];   // 50MB  bf16(W^T)
__device__ __nv_bfloat16 g_B1[(long)NGATE * KDIM];   // 50MB  bf16(W^T - B0)
__device__ float g_G[(long)BDIM * NGATE];            // 96MB  raw gate pre-activations

// ---------------- helpers ----------------
__device__ __forceinline__ uint32_t smem_u32(const void* p) {
    uint32_t a;
    asm("{ .reg .u64 t; cvta.to.shared.u64 t, %1; cvt.u32.u64 %0, t; }" : "=r"(a) : "l"(p));
    return a;
}
__device__ __forceinline__ void cp16(uint32_t dst, const void* src) {
    asm volatile("cp.async.cg.shared.global [%0], [%1], 16;" :: "r"(dst), "l"(src) : "memory");
}
__device__ __forceinline__ void cp_commit() {
    asm volatile("cp.async.commit_group;" ::: "memory");
}
template <int N>
__device__ __forceinline__ void cp_wait() {
    asm volatile("cp.async.wait_group %0;" :: "n"(N) : "memory");
}
__device__ __forceinline__ void ldsm4(uint32_t& r0, uint32_t& r1, uint32_t& r2, uint32_t& r3,
                                      uint32_t addr) {
    asm volatile("ldmatrix.sync.aligned.m8n8.x4.shared.b16 {%0,%1,%2,%3}, [%4];"
                 : "=r"(r0), "=r"(r1), "=r"(r2), "=r"(r3) : "r"(addr));
}
__device__ __forceinline__ void mma_bf16(float* c, const uint32_t* a, const uint32_t* b) {
    asm volatile(
        "mma.sync.aligned.m16n8k16.row.col.f32.bf16.bf16.f32 "
        "{%0,%1,%2,%3}, {%4,%5,%6,%7}, {%8,%9}, {%0,%1,%2,%3};"
        : "+f"(c[0]), "+f"(c[1]), "+f"(c[2]), "+f"(c[3])
        : "r"(a[0]), "r"(a[1]), "r"(a[2]), "r"(a[3]), "r"(b[0]), "r"(b[1]));
}
__device__ __forceinline__ void split2(float x, __nv_bfloat16& h0, __nv_bfloat16& h1) {
    h0 = __float2bfloat16_rn(x);
    h1 = __float2bfloat16_rn(x - __bfloat162float(h0));
}

// ---------------- prologue: pack & split X = [old_h | input] ----------------
__global__ void pack_split_x(const float* __restrict__ old_h, const float* __restrict__ input,
                             __nv_bfloat16* __restrict__ A0, __nv_bfloat16* __restrict__ A1) {
    long i = (long)blockIdx.x * blockDim.x + threadIdx.x;   // float4 units, 4096*1024
    int m = (int)(i >> 10);
    int kq = (int)(i & 1023);
    float4 v = (kq < 512) ? reinterpret_cast<const float4*>(old_h)[(long)m * 512 + kq]
                          : reinterpret_cast<const float4*>(input)[(long)m * 512 + (kq - 512)];
    __nv_bfloat16 h0[4], h1[4];
    split2(v.x, h0[0], h1[0]);
    split2(v.y, h0[1], h1[1]);
    split2(v.z, h0[2], h1[2]);
    split2(v.w, h0[3], h1[3]);
    *reinterpret_cast<uint2*>(&A0[4 * i]) = *reinterpret_cast<uint2*>(h0);
    *reinterpret_cast<uint2*>(&A1[4 * i]) = *reinterpret_cast<uint2*>(h1);
}

// ---------------- prologue: transpose & split W -> Wt[n][k] ----------------
__global__ void split_w_kernel(const float* __restrict__ W,
                               __nv_bfloat16* __restrict__ B0, __nv_bfloat16* __restrict__ B1) {
    __shared__ float tile[32][33];
    int n0 = blockIdx.x * 32, k0 = blockIdx.y * 32;
    int tx = threadIdx.x, ty = threadIdx.y;
#pragma unroll
    for (int i = 0; i < 32; i += 8)
        tile[ty + i][tx] = W[(long)(k0 + ty + i) * NGATE + n0 + tx];
    __syncthreads();
#pragma unroll
    for (int i = 0; i < 32; i += 8) {
        long n = n0 + ty + i, k = k0 + tx;
        __nv_bfloat16 h0, h1;
        split2(tile[tx][ty + i], h0, h1);
        B0[n * KDIM + k] = h0;
        B1[n * KDIM + k] = h1;
    }
}

// ---------------- main GEMM: G = sum of 3 bf16 products (K tripled) ----------------
// CTA 256x96, 8 warps 4(m)x2(n), warp tile 64x48 (4 mtiles x 6 ntiles of m16n8).
__global__ void __launch_bounds__(256, 1) gemm_kernel(
    const __nv_bfloat16* __restrict__ A0, const __nv_bfloat16* __restrict__ A1,
    const __nv_bfloat16* __restrict__ B0, const __nv_bfloat16* __restrict__ B1,
    float* __restrict__ G) {
    extern __shared__ char smem[];
    const uint32_t sbase = smem_u32(smem);

    const int tid = threadIdx.x;
    const int warp = tid >> 5, lane = tid & 31;
    const int wm = warp >> 1, wn = warp & 1;
    const int g = lane >> 2, t4 = lane & 3;
    const long m0 = (long)blockIdx.x * BM;
    const long n0 = (long)blockIdx.y * BN;

    float acc[4][6][4];
#pragma unroll
    for (int i = 0; i < 4; i++)
#pragma unroll
        for (int j = 0; j < 6; j++)
#pragma unroll
            for (int r = 0; r < 4; r++) acc[i][j][r] = 0.0f;

    // per-lane ldmatrix address offsets (within a stage)
    const uint32_t a_off = (uint32_t)(wm * 64 + (lane & 15)) * ROWB + ((lane >> 4) << 4);
    const uint32_t b_off =
        (uint32_t)(wn * 48 + (lane & 7) + ((lane >> 4) << 3)) * ROWB + (((lane >> 3) & 1) << 4);

    // stage loader: A 256 rows x 128B (8 chunks/row), B 96 rows x 128B (3 chunks/thread)
    auto issue_stage = [&](int t) {
        int slot = t % STAGES;
        int phase = t >> 6;               // t / KT
        long kk = (long)(t & (KT - 1)) * BK;
        const __nv_bfloat16* pA = (phase == 1) ? A1 : A0;
        const __nv_bfloat16* pB = (phase == 2) ? B1 : B0;
        uint32_t sA = sbase + slot * STAGE_BYTES;
        uint32_t sB = sA + A_BYTES;
#pragma unroll
        for (int i = 0; i < 8; i++) {
            int q = tid + i * 256;
            int row = q >> 3, cw = q & 7;
            cp16(sA + row * ROWB + cw * 16, pA + (m0 + row) * KDIM + kk + cw * 8);
        }
#pragma unroll
        for (int i = 0; i < 3; i++) {
            int q = tid + i * 256;
            int row = q >> 3, cw = q & 7;
            cp16(sB + row * ROWB + cw * 16, pB + (n0 + row) * KDIM + kk + cw * 8);
        }
    };

#pragma unroll
    for (int s = 0; s < STAGES - 1; s++) {
        issue_stage(s);
        cp_commit();
    }

    uint32_t a[2][4][4], b[2][6][2];

    for (int t = 0; t < TOT_ITERS; t++) {
        cp_wait<STAGES - 2>();
        __syncthreads();

        if (t + STAGES - 1 < TOT_ITERS) issue_stage(t + STAGES - 1);
        cp_commit();

        uint32_t sA = sbase + (t % STAGES) * STAGE_BYTES;
        uint32_t sB = sA + A_BYTES;

        // double-buffered fragment pipeline over the 4 k16 slices
#pragma unroll
        for (int i = 0; i < 4; i++)
            ldsm4(a[0][i][0], a[0][i][1], a[0][i][2], a[0][i][3],
                  sA + a_off + (uint32_t)i * (16 * ROWB));
#pragma unroll
        for (int jj = 0; jj < 3; jj++)
            ldsm4(b[0][2 * jj][0], b[0][2 * jj][1], b[0][2 * jj + 1][0], b[0][2 * jj + 1][1],
                  sB + b_off + (uint32_t)jj * (16 * ROWB));

#pragma unroll
        for (int s = 0; s < 4; s++) {
            const int cur = s & 1, nxt = cur ^ 1;
            if (s < 3) {
#pragma unroll
                for (int i = 0; i < 4; i++)
                    ldsm4(a[nxt][i][0], a[nxt][i][1], a[nxt][i][2], a[nxt][i][3],
                          sA + a_off + (uint32_t)i * (16 * ROWB) + (uint32_t)(s + 1) * 32);
#pragma unroll
                for (int jj = 0; jj < 3; jj++)
                    ldsm4(b[nxt][2 * jj][0], b[nxt][2 * jj][1],
                          b[nxt][2 * jj + 1][0], b[nxt][2 * jj + 1][1],
                          sB + b_off + (uint32_t)jj * (16 * ROWB) + (uint32_t)(s + 1) * 32);
            }
#pragma unroll
            for (int i = 0; i < 4; i++)
#pragma unroll
                for (int j = 0; j < 6; j++) mma_bf16(acc[i][j], a[cur][i], b[cur][j]);
        }
    }

    // store raw gates (fp32)
#pragma unroll
    for (int i = 0; i < 4; i++) {
        long row0 = m0 + wm * 64 + i * 16 + g;
#pragma unroll
        for (int j = 0; j < 6; j++) {
            long col = n0 + wn * 48 + j * 8 + 2 * t4;
            *reinterpret_cast<float2*>(&G[row0 * NGATE + col]) =
                make_float2(acc[i][j][0], acc[i][j][1]);
            *reinterpret_cast<float2*>(&G[(row0 + 8) * NGATE + col]) =
                make_float2(acc[i][j][2], acc[i][j][3]);
        }
    }
}

// ---------------- fused pointwise epilogue ----------------
__global__ void epilogue_kernel(const float* __restrict__ G, const float* __restrict__ bias,
                                const float* __restrict__ old_c, float* __restrict__ out) {
    long i = (long)blockIdx.x * blockDim.x + threadIdx.x;   // float4 units, 4096*512
    int m = (int)(i >> 9);
    int sq = (int)(i & 511);

    const float4* G4 = reinterpret_cast<const float4*>(G);
    const float4* B4 = reinterpret_cast<const float4*>(bias);
    float4 gi = G4[(long)m * 1536 + sq];
    float4 go = G4[(long)m * 1536 + 512 + sq];
    float4 gc = G4[(long)m * 1536 + 1024 + sq];
    float4 bi = B4[sq];
    float4 bo = B4[512 + sq];
    float4 bc = B4[1024 + sq];
    float4 oc = reinterpret_cast<const float4*>(old_c)[i];

    float4 nh, nc;
    {
        float vi, vo, vc, ig, og, cc, cell;
#define LANE(f)                                                     \
        vi = gi.f + bi.f; vo = go.f + bo.f; vc = gc.f + bc.f;       \
        ig = 1.0f / (1.0f + expf(-vi));                             \
        og = 1.0f / (1.0f + expf(-vo));                             \
        cc = (vc > 0.0f) ? vc : expm1f(vc);                         \
        cell = oc.f + cc * ig;                                      \
        nc.f = cell;                                                \
        nh.f = tanhf(cell) * og;
        LANE(x) LANE(y) LANE(z) LANE(w)
#undef LANE
    }
    reinterpret_cast<float4*>(out)[i] = nh;
    reinterpret_cast<float4*>(out)[HSIZE / 4 + i] = nc;
}

// ---------------- host ----------------
extern "C" void kernel_launch(void* const* d_in, const int* in_sizes, int n_in,
                              void* d_out, int out_size) {
    const float* W     = (const float*)d_in[0];   // (4096, 6144)
    const float* bias  = (const float*)d_in[1];   // (6144,)
    const float* input = (const float*)d_in[2];   // (4096, 2048)
    const float* old_h = (const float*)d_in[3];   // (4096, 2048)
    const float* old_c = (const float*)d_in[4];   // (4096, 2048)
    float* out = (float*)d_out;                   // [new_h | new_cell]

    void *pA0, *pA1, *pB0, *pB1, *pG;
    cudaGetSymbolAddress(&pA0, g_A0);
    cudaGetSymbolAddress(&pA1, g_A1);
    cudaGetSymbolAddress(&pB0, g_B0);
    cudaGetSymbolAddress(&pB1, g_B1);
    cudaGetSymbolAddress(&pG, g_G);

    pack_split_x<<<16384, 256>>>(old_h, input, (__nv_bfloat16*)pA0, (__nv_bfloat16*)pA1);
    split_w_kernel<<<dim3(NGATE / 32, KDIM / 32), dim3(32, 8)>>>(
        W, (__nv_bfloat16*)pB0, (__nv_bfloat16*)pB1);

    cudaFuncSetAttribute(gemm_kernel, cudaFuncAttributeMaxDynamicSharedMemorySize, SMEM_TOTAL);
    gemm_kernel<<<dim3(BDIM / BM, NGATE / BN), 256, SMEM_TOTAL>>>(
        (const __nv_bfloat16*)pA0, (const __nv_bfloat16*)pA1,
        (const __nv_bfloat16*)pB0, (const __nv_bfloat16*)pB1, (float*)pG);

    epilogue_kernel<<<8192, 256>>>((const float*)pG, bias, old_c, out);
}

// round 6
// speedup vs baseline: 1.3851x; 1.1180x over previous
#include <cuda_runtime.h>
#include <cuda_bf16.h>
#include <cstdint>
#include <math.h>

// ---------------- problem constants ----------------
#define BDIM   4096          // batch rows
#define KDIM   4096          // F + S
#define NGATE  6144          // 3*S
#define SDIM   2048
#define HSIZE  8388608L      // B*S

// ---------------- GEMM tile config (bf16 mma.sync m16n8k16, 3-product split) ----------------
#define BM 128
#define BN 96                // 32 x 64 = 2048 CTAs, 2 CTAs/SM -> 6.92 eff waves
#define BK 64                // 64 bf16 along k per chunk = 4 k16 slices
#define KT (KDIM / BK)       // 64 chunks per product phase
#define NPHASE 3             // A0B0 + A1B0 + A0B1
#define TOT_ITERS (NPHASE * KT)   // 192
#define STAGES 3
#define NTHREADS 128

// smem layout: row stride 144 bytes (128 data + 16 pad) -> conflict-free ldmatrix + cp.async
#define ROWB 144
#define A_BYTES (BM * ROWB)          // 18432
#define B_BYTES (BN * ROWB)          // 13824
#define STAGE_BYTES (A_BYTES + B_BYTES)   // 32256
#define SMEM_TOTAL (STAGES * STAGE_BYTES) // 96768 (x2 CTAs = 193.5KB/SM)

// ---------------- scratch (no cudaMalloc allowed) ----------------
__device__ __nv_bfloat16 g_A0[(long)BDIM * KDIM];    // 32MB  bf16(X)
__device__ __nv_bfloat16 g_A1[(long)BDIM * KDIM];    // 32MB  bf16(X - A0)
__device__ __nv_bfloat16 g_B0[(long)NGATE * KDIM];   // 50MB  bf16(W^T)
__device__ __nv_bfloat16 g_B1[(long)NGATE * KDIM];   // 50MB  bf16(W^T - B0)
__device__ float g_G[(long)BDIM * NGATE];            // 96MB  raw gate pre-activations

// ---------------- helpers ----------------
__device__ __forceinline__ uint32_t smem_u32(const void* p) {
    uint32_t a;
    asm("{ .reg .u64 t; cvta.to.shared.u64 t, %1; cvt.u32.u64 %0, t; }" : "=r"(a) : "l"(p));
    return a;
}
__device__ __forceinline__ void cp16(uint32_t dst, const void* src) {
    asm volatile("cp.async.cg.shared.global [%0], [%1], 16;" :: "r"(dst), "l"(src) : "memory");
}
__device__ __forceinline__ void cp_commit() {
    asm volatile("cp.async.commit_group;" ::: "memory");
}
template <int N>
__device__ __forceinline__ void cp_wait() {
    asm volatile("cp.async.wait_group %0;" :: "n"(N) : "memory");
}
__device__ __forceinline__ void ldsm4(uint32_t& r0, uint32_t& r1, uint32_t& r2, uint32_t& r3,
                                      uint32_t addr) {
    asm volatile("ldmatrix.sync.aligned.m8n8.x4.shared.b16 {%0,%1,%2,%3}, [%4];"
                 : "=r"(r0), "=r"(r1), "=r"(r2), "=r"(r3) : "r"(addr));
}
__device__ __forceinline__ void mma_bf16(float* c, const uint32_t* a, const uint32_t* b) {
    asm volatile(
        "mma.sync.aligned.m16n8k16.row.col.f32.bf16.bf16.f32 "
        "{%0,%1,%2,%3}, {%4,%5,%6,%7}, {%8,%9}, {%0,%1,%2,%3};"
        : "+f"(c[0]), "+f"(c[1]), "+f"(c[2]), "+f"(c[3])
        : "r"(a[0]), "r"(a[1]), "r"(a[2]), "r"(a[3]), "r"(b[0]), "r"(b[1]));
}
__device__ __forceinline__ void split2(float x, __nv_bfloat16& h0, __nv_bfloat16& h1) {
    h0 = __float2bfloat16_rn(x);
    h1 = __float2bfloat16_rn(x - __bfloat162float(h0));
}

// ---------------- prologue: pack & split X = [old_h | input] ----------------
__global__ void pack_split_x(const float* __restrict__ old_h, const float* __restrict__ input,
                             __nv_bfloat16* __restrict__ A0, __nv_bfloat16* __restrict__ A1) {
    long i = (long)blockIdx.x * blockDim.x + threadIdx.x;   // float4 units, 4096*1024
    int m = (int)(i >> 10);
    int kq = (int)(i & 1023);
    float4 v = (kq < 512) ? reinterpret_cast<const float4*>(old_h)[(long)m * 512 + kq]
                          : reinterpret_cast<const float4*>(input)[(long)m * 512 + (kq - 512)];
    __nv_bfloat16 h0[4], h1[4];
    split2(v.x, h0[0], h1[0]);
    split2(v.y, h0[1], h1[1]);
    split2(v.z, h0[2], h1[2]);
    split2(v.w, h0[3], h1[3]);
    *reinterpret_cast<uint2*>(&A0[4 * i]) = *reinterpret_cast<uint2*>(h0);
    *reinterpret_cast<uint2*>(&A1[4 * i]) = *reinterpret_cast<uint2*>(h1);
}

// ---------------- prologue: transpose & split W -> Wt[n][k] ----------------
__global__ void split_w_kernel(const float* __restrict__ W,
                               __nv_bfloat16* __restrict__ B0, __nv_bfloat16* __restrict__ B1) {
    __shared__ float tile[32][33];
    int n0 = blockIdx.x * 32, k0 = blockIdx.y * 32;
    int tx = threadIdx.x, ty = threadIdx.y;
#pragma unroll
    for (int i = 0; i < 32; i += 8)
        tile[ty + i][tx] = W[(long)(k0 + ty + i) * NGATE + n0 + tx];
    __syncthreads();
#pragma unroll
    for (int i = 0; i < 32; i += 8) {
        long n = n0 + ty + i, k = k0 + tx;
        __nv_bfloat16 h0, h1;
        split2(tile[tx][ty + i], h0, h1);
        B0[n * KDIM + k] = h0;
        B1[n * KDIM + k] = h1;
    }
}

// ---------------- main GEMM: G = sum of 3 bf16 products (K tripled) ----------------
// CTA 128x96, 4 warps 2(m)x2(n), warp tile 64x48 (4 mtiles x 6 ntiles of m16n8).
// 2 CTAs co-resident per SM to hide the per-chunk cp_wait/__syncthreads bubble.
__global__ void __launch_bounds__(NTHREADS, 2) gemm_kernel(
    const __nv_bfloat16* __restrict__ A0, const __nv_bfloat16* __restrict__ A1,
    const __nv_bfloat16* __restrict__ B0, const __nv_bfloat16* __restrict__ B1,
    float* __restrict__ G) {
    extern __shared__ char smem[];
    const uint32_t sbase = smem_u32(smem);

    const int tid = threadIdx.x;
    const int warp = tid >> 5, lane = tid & 31;
    const int wm = warp >> 1, wn = warp & 1;
    const int g = lane >> 2, t4 = lane & 3;
    const long m0 = (long)blockIdx.x * BM;
    const long n0 = (long)blockIdx.y * BN;

    float acc[4][6][4];
#pragma unroll
    for (int i = 0; i < 4; i++)
#pragma unroll
        for (int j = 0; j < 6; j++)
#pragma unroll
            for (int r = 0; r < 4; r++) acc[i][j][r] = 0.0f;

    // per-lane ldmatrix address offsets (within a stage)
    const uint32_t a_off = (uint32_t)(wm * 64 + (lane & 15)) * ROWB + ((lane >> 4) << 4);
    const uint32_t b_off =
        (uint32_t)(wn * 48 + (lane & 7) + ((lane >> 4) << 3)) * ROWB + (((lane >> 3) & 1) << 4);

    // stage loader: A 128 rows x 8 chunks (8/thread), B 96 rows x 8 chunks (6/thread)
    auto issue_stage = [&](int t) {
        int slot = t % STAGES;
        int phase = t >> 6;               // t / KT
        long kk = (long)(t & (KT - 1)) * BK;
        const __nv_bfloat16* pA = (phase == 1) ? A1 : A0;
        const __nv_bfloat16* pB = (phase == 2) ? B1 : B0;
        uint32_t sA = sbase + slot * STAGE_BYTES;
        uint32_t sB = sA + A_BYTES;
#pragma unroll
        for (int i = 0; i < 8; i++) {
            int q = tid + i * NTHREADS;
            int row = q >> 3, cw = q & 7;
            cp16(sA + row * ROWB + cw * 16, pA + (m0 + row) * KDIM + kk + cw * 8);
        }
#pragma unroll
        for (int i = 0; i < 6; i++) {
            int q = tid + i * NTHREADS;
            int row = q >> 3, cw = q & 7;
            cp16(sB + row * ROWB + cw * 16, pB + (n0 + row) * KDIM + kk + cw * 8);
        }
    };

#pragma unroll
    for (int s = 0; s < STAGES - 1; s++) {
        issue_stage(s);
        cp_commit();
    }

    uint32_t a[2][4][4], b[2][6][2];

    for (int t = 0; t < TOT_ITERS; t++) {
        cp_wait<STAGES - 2>();
        __syncthreads();

        if (t + STAGES - 1 < TOT_ITERS) issue_stage(t + STAGES - 1);
        cp_commit();

        uint32_t sA = sbase + (t % STAGES) * STAGE_BYTES;
        uint32_t sB = sA + A_BYTES;

        // double-buffered fragment pipeline over the 4 k16 slices
#pragma unroll
        for (int i = 0; i < 4; i++)
            ldsm4(a[0][i][0], a[0][i][1], a[0][i][2], a[0][i][3],
                  sA + a_off + (uint32_t)i * (16 * ROWB));
#pragma unroll
        for (int jj = 0; jj < 3; jj++)
            ldsm4(b[0][2 * jj][0], b[0][2 * jj][1], b[0][2 * jj + 1][0], b[0][2 * jj + 1][1],
                  sB + b_off + (uint32_t)jj * (16 * ROWB));

#pragma unroll
        for (int s = 0; s < 4; s++) {
            const int cur = s & 1, nxt = cur ^ 1;
            if (s < 3) {
#pragma unroll
                for (int i = 0; i < 4; i++)
                    ldsm4(a[nxt][i][0], a[nxt][i][1], a[nxt][i][2], a[nxt][i][3],
                          sA + a_off + (uint32_t)i * (16 * ROWB) + (uint32_t)(s + 1) * 32);
#pragma unroll
                for (int jj = 0; jj < 3; jj++)
                    ldsm4(b[nxt][2 * jj][0], b[nxt][2 * jj][1],
                          b[nxt][2 * jj + 1][0], b[nxt][2 * jj + 1][1],
                          sB + b_off + (uint32_t)jj * (16 * ROWB) + (uint32_t)(s + 1) * 32);
            }
#pragma unroll
            for (int i = 0; i < 4; i++)
#pragma unroll
                for (int j = 0; j < 6; j++) mma_bf16(acc[i][j], a[cur][i], b[cur][j]);
        }
    }

    // store raw gates (fp32)
#pragma unroll
    for (int i = 0; i < 4; i++) {
        long row0 = m0 + wm * 64 + i * 16 + g;
#pragma unroll
        for (int j = 0; j < 6; j++) {
            long col = n0 + wn * 48 + j * 8 + 2 * t4;
            *reinterpret_cast<float2*>(&G[row0 * NGATE + col]) =
                make_float2(acc[i][j][0], acc[i][j][1]);
            *reinterpret_cast<float2*>(&G[(row0 + 8) * NGATE + col]) =
                make_float2(acc[i][j][2], acc[i][j][3]);
        }
    }
}

// ---------------- fused pointwise epilogue ----------------
__global__ void epilogue_kernel(const float* __restrict__ G, const float* __restrict__ bias,
                                const float* __restrict__ old_c, float* __restrict__ out) {
    long i = (long)blockIdx.x * blockDim.x + threadIdx.x;   // float4 units, 4096*512
    int m = (int)(i >> 9);
    int sq = (int)(i & 511);

    const float4* G4 = reinterpret_cast<const float4*>(G);
    const float4* B4 = reinterpret_cast<const float4*>(bias);
    float4 gi = G4[(long)m * 1536 + sq];
    float4 go = G4[(long)m * 1536 + 512 + sq];
    float4 gc = G4[(long)m * 1536 + 1024 + sq];
    float4 bi = B4[sq];
    float4 bo = B4[512 + sq];
    float4 bc = B4[1024 + sq];
    float4 oc = reinterpret_cast<const float4*>(old_c)[i];

    float4 nh, nc;
    {
        float vi, vo, vc, ig, og, cc, cell;
#define LANE(f)                                                     \
        vi = gi.f + bi.f; vo = go.f + bo.f; vc = gc.f + bc.f;       \
        ig = 1.0f / (1.0f + expf(-vi));                             \
        og = 1.0f / (1.0f + expf(-vo));                             \
        cc = (vc > 0.0f) ? vc : expm1f(vc);                         \
        cell = oc.f + cc * ig;                                      \
        nc.f = cell;                                                \
        nh.f = tanhf(cell) * og;
        LANE(x) LANE(y) LANE(z) LANE(w)
#undef LANE
    }
    reinterpret_cast<float4*>(out)[i] = nh;
    reinterpret_cast<float4*>(out)[HSIZE / 4 + i] = nc;
}

// ---------------- host ----------------
extern "C" void kernel_launch(void* const* d_in, const int* in_sizes, int n_in,
                              void* d_out, int out_size) {
    const float* W     = (const float*)d_in[0];   // (4096, 6144)
    const float* bias  = (const float*)d_in[1];   // (6144,)
    const float* input = (const float*)d_in[2];   // (4096, 2048)
    const float* old_h = (const float*)d_in[3];   // (4096, 2048)
    const float* old_c = (const float*)d_in[4];   // (4096, 2048)
    float* out = (float*)d_out;                   // [new_h | new_cell]

    void *pA0, *pA1, *pB0, *pB1, *pG;
    cudaGetSymbolAddress(&pA0, g_A0);
    cudaGetSymbolAddress(&pA1, g_A1);
    cudaGetSymbolAddress(&pB0, g_B0);
    cudaGetSymbolAddress(&pB1, g_B1);
    cudaGetSymbolAddress(&pG, g_G);

    pack_split_x<<<16384, 256>>>(old_h, input, (__nv_bfloat16*)pA0, (__nv_bfloat16*)pA1);
    split_w_kernel<<<dim3(NGATE / 32, KDIM / 32), dim3(32, 8)>>>(
        W, (__nv_bfloat16*)pB0, (__nv_bfloat16*)pB1);

    cudaFuncSetAttribute(gemm_kernel, cudaFuncAttributeMaxDynamicSharedMemorySize, SMEM_TOTAL);
    gemm_kernel<<<dim3(BDIM / BM, NGATE / BN), NTHREADS, SMEM_TOTAL>>>(
        (const __nv_bfloat16*)pA0, (const __nv_bfloat16*)pA1,
        (const __nv_bfloat16*)pB0, (const __nv_bfloat16*)pB1, (float*)pG);

    epilogue_kernel<<<8192, 256>>>((const float*)pG, bias, old_c, out);
}

// round 7
// speedup vs baseline: 1.4677x; 1.0596x over previous
#include <cuda_runtime.h>
#include <cuda_bf16.h>
#include <cstdint>
#include <math.h>

// ---------------- problem constants ----------------
#define BDIM   4096          // batch rows
#define KDIM   4096          // F + S
#define NGATE  6144          // 3*S
#define SDIM   2048
#define HSIZE  8388608L      // B*S

// ---------------- GEMM tile config ----------------
#define BM 128
#define BNS 32               // state-columns per CTA; B tile = 3 gates x 32 = 96 rows
#define BNROWS 96
#define BK 64                // 64 bf16 along k per chunk = 4 k16 slices
#define KT (KDIM / BK)       // 64 chunks per product phase
#define NPHASE 3             // A0B0 + A1B0 + A0B1
#define TOT_ITERS (NPHASE * KT)   // 192
#define STAGES 2
#define NTHREADS 128

// smem layout: row stride 144 bytes (128 data + 16 pad) -> conflict-free ldmatrix + cp.async
#define ROWB 144
#define A_BYTES (BM * ROWB)               // 18432
#define B_BYTES (BNROWS * ROWB)           // 13824
#define STAGE_BYTES (A_BYTES + B_BYTES)   // 32256
#define SMEM_TOTAL (STAGES * STAGE_BYTES) // 64512 (x3 CTAs = 193.5KB/SM)

// ---------------- scratch (no cudaMalloc allowed) ----------------
__device__ __nv_bfloat16 g_A0[(long)BDIM * KDIM];    // 32MB  bf16(X)
__device__ __nv_bfloat16 g_A1[(long)BDIM * KDIM];    // 32MB  bf16(X - A0)
__device__ __nv_bfloat16 g_B0[(long)NGATE * KDIM];   // 50MB  bf16(W^T)
__device__ __nv_bfloat16 g_B1[(long)NGATE * KDIM];   // 50MB  bf16(W^T - B0)

// ---------------- helpers ----------------
__device__ __forceinline__ uint32_t smem_u32(const void* p) {
    uint32_t a;
    asm("{ .reg .u64 t; cvta.to.shared.u64 t, %1; cvt.u32.u64 %0, t; }" : "=r"(a) : "l"(p));
    return a;
}
__device__ __forceinline__ void cp16(uint32_t dst, const void* src) {
    asm volatile("cp.async.cg.shared.global [%0], [%1], 16;" :: "r"(dst), "l"(src) : "memory");
}
__device__ __forceinline__ void cp_commit() {
    asm volatile("cp.async.commit_group;" ::: "memory");
}
template <int N>
__device__ __forceinline__ void cp_wait() {
    asm volatile("cp.async.wait_group %0;" :: "n"(N) : "memory");
}
__device__ __forceinline__ void ldsm4(uint32_t& r0, uint32_t& r1, uint32_t& r2, uint32_t& r3,
                                      uint32_t addr) {
    asm volatile("ldmatrix.sync.aligned.m8n8.x4.shared.b16 {%0,%1,%2,%3}, [%4];"
                 : "=r"(r0), "=r"(r1), "=r"(r2), "=r"(r3) : "r"(addr));
}
__device__ __forceinline__ void mma_bf16(float* c, const uint32_t* a, const uint32_t* b) {
    asm volatile(
        "mma.sync.aligned.m16n8k16.row.col.f32.bf16.bf16.f32 "
        "{%0,%1,%2,%3}, {%4,%5,%6,%7}, {%8,%9}, {%0,%1,%2,%3};"
        : "+f"(c[0]), "+f"(c[1]), "+f"(c[2]), "+f"(c[3])
        : "r"(a[0]), "r"(a[1]), "r"(a[2]), "r"(a[3]), "r"(b[0]), "r"(b[1]));
}
__device__ __forceinline__ void split2(float x, __nv_bfloat16& h0, __nv_bfloat16& h1) {
    h0 = __float2bfloat16_rn(x);
    h1 = __float2bfloat16_rn(x - __bfloat162float(h0));
}

// ---------------- prologue: pack & split X = [old_h | input] ----------------
__global__ void pack_split_x(const float* __restrict__ old_h, const float* __restrict__ input,
                             __nv_bfloat16* __restrict__ A0, __nv_bfloat16* __restrict__ A1) {
    long i = (long)blockIdx.x * blockDim.x + threadIdx.x;   // float4 units, 4096*1024
    int m = (int)(i >> 10);
    int kq = (int)(i & 1023);
    float4 v = (kq < 512) ? reinterpret_cast<const float4*>(old_h)[(long)m * 512 + kq]
                          : reinterpret_cast<const float4*>(input)[(long)m * 512 + (kq - 512)];
    __nv_bfloat16 h0[4], h1[4];
    split2(v.x, h0[0], h1[0]);
    split2(v.y, h0[1], h1[1]);
    split2(v.z, h0[2], h1[2]);
    split2(v.w, h0[3], h1[3]);
    *reinterpret_cast<uint2*>(&A0[4 * i]) = *reinterpret_cast<uint2*>(h0);
    *reinterpret_cast<uint2*>(&A1[4 * i]) = *reinterpret_cast<uint2*>(h1);
}

// ---------------- prologue: transpose & split W -> Wt[n][k] ----------------
__global__ void split_w_kernel(const float* __restrict__ W,
                               __nv_bfloat16* __restrict__ B0, __nv_bfloat16* __restrict__ B1) {
    __shared__ float tile[32][33];
    int n0 = blockIdx.x * 32, k0 = blockIdx.y * 32;
    int tx = threadIdx.x, ty = threadIdx.y;
#pragma unroll
    for (int i = 0; i < 32; i += 8)
        tile[ty + i][tx] = W[(long)(k0 + ty + i) * NGATE + n0 + tx];
    __syncthreads();
#pragma unroll
    for (int i = 0; i < 32; i += 8) {
        long n = n0 + ty + i, k = k0 + tx;
        __nv_bfloat16 h0, h1;
        split2(tile[tx][ty + i], h0, h1);
        B0[n * KDIM + k] = h0;
        B1[n * KDIM + k] = h1;
    }
}

// ---------------- fused GEMM + LLTM epilogue ----------------
// CTA computes 128 rows x 32 state-cols x ALL 3 gates. 4 warps 4(m)x1(n),
// warp tile 32(m) x 96(nrows). acc[2 mtiles][12 ntiles][4]. 3 CTAs/SM.
__global__ void __launch_bounds__(NTHREADS, 3) lltm_fused_kernel(
    const __nv_bfloat16* __restrict__ A0, const __nv_bfloat16* __restrict__ A1,
    const __nv_bfloat16* __restrict__ B0, const __nv_bfloat16* __restrict__ B1,
    const float* __restrict__ bias, const float* __restrict__ old_c,
    float* __restrict__ out) {
    extern __shared__ char smem[];
    const uint32_t sbase = smem_u32(smem);

    const int tid = threadIdx.x;
    const int warp = tid >> 5, lane = tid & 31;
    const int g = lane >> 2, t4 = lane & 3;
    const long m0 = (long)blockIdx.x * BM;
    const int n0s = blockIdx.y * BNS;        // state-column base (0..2047)

    float acc[2][12][4];
#pragma unroll
    for (int i = 0; i < 2; i++)
#pragma unroll
        for (int j = 0; j < 12; j++)
#pragma unroll
            for (int r = 0; r < 4; r++) acc[i][j][r] = 0.0f;

    // per-lane ldmatrix offsets
    const uint32_t a_off = (uint32_t)(warp * 32 + (lane & 15)) * ROWB + ((lane >> 4) << 4);
    const uint32_t b_off =
        (uint32_t)((lane & 7) + ((lane >> 4) << 3)) * ROWB + (((lane >> 3) & 1) << 4);

    // stage loader: A 128 rows (8 chunks/thread), B 96 rows = 3 gates x 32 (6 chunks/thread)
    auto issue_stage = [&](int t) {
        int slot = t & (STAGES - 1);
        int phase = t >> 6;               // t / KT
        long kk = (long)(t & (KT - 1)) * BK;
        const __nv_bfloat16* pA = (phase == 1) ? A1 : A0;
        const __nv_bfloat16* pB = (phase == 2) ? B1 : B0;
        uint32_t sA = sbase + slot * STAGE_BYTES;
        uint32_t sB = sA + A_BYTES;
#pragma unroll
        for (int i = 0; i < 8; i++) {
            int q = tid + i * NTHREADS;
            int row = q >> 3, cw = q & 7;
            cp16(sA + row * ROWB + cw * 16, pA + (m0 + row) * KDIM + kk + cw * 8);
        }
#pragma unroll
        for (int i = 0; i < 6; i++) {
            int q = tid + i * NTHREADS;
            int row = q >> 3, cw = q & 7;        // row 0..95
            long grow = (long)(row >> 5) * SDIM + n0s + (row & 31);
            cp16(sB + row * ROWB + cw * 16, pB + grow * KDIM + kk + cw * 8);
        }
    };

    issue_stage(0);
    cp_commit();

    for (int t = 0; t < TOT_ITERS; t++) {
        cp_wait<0>();
        __syncthreads();

        if (t + 1 < TOT_ITERS) issue_stage(t + 1);
        cp_commit();

        uint32_t sA = sbase + (t & (STAGES - 1)) * STAGE_BYTES;
        uint32_t sB = sA + A_BYTES;

#pragma unroll
        for (int s = 0; s < 4; s++) {            // 4 k16 slices
            uint32_t a[2][4];
#pragma unroll
            for (int i = 0; i < 2; i++)
                ldsm4(a[i][0], a[i][1], a[i][2], a[i][3],
                      sA + a_off + (uint32_t)i * (16 * ROWB) + (uint32_t)s * 32);
            uint32_t b[12][2];
#pragma unroll
            for (int jj = 0; jj < 6; jj++)
                ldsm4(b[2 * jj][0], b[2 * jj][1], b[2 * jj + 1][0], b[2 * jj + 1][1],
                      sB + b_off + (uint32_t)jj * (16 * ROWB) + (uint32_t)s * 32);
#pragma unroll
            for (int i = 0; i < 2; i++)
#pragma unroll
                for (int j = 0; j < 12; j++) mma_bf16(acc[i][j], a[i], b[j]);
        }
    }

    // ---- fused LLTM epilogue ----
    // acc n-tile j: gate = j/4, state col = n0s + (j%4)*8 + 2*t4 (+1)
#pragma unroll
    for (int i = 0; i < 2; i++) {
        long row0 = m0 + warp * 32 + i * 16 + g;
#pragma unroll
        for (int sj = 0; sj < 4; sj++) {
            int col = n0s + sj * 8 + 2 * t4;
            float2 bi = *reinterpret_cast<const float2*>(&bias[col]);
            float2 bo = *reinterpret_cast<const float2*>(&bias[SDIM + col]);
            float2 bc = *reinterpret_cast<const float2*>(&bias[2 * SDIM + col]);
            const float* ai = acc[i][sj];
            const float* ao = acc[i][sj + 4];
            const float* ac = acc[i][sj + 8];
#pragma unroll
            for (int h = 0; h < 2; h++) {        // h=0: row0, h=1: row0+8
                long row = row0 + 8 * h;
                float2 oc = *reinterpret_cast<const float2*>(&old_c[row * SDIM + col]);
                float2 nh, ncell;
#define LANE(f, idx)                                                    \
                {                                                       \
                    float vi = ai[2 * h + idx] + bi.f;                  \
                    float vo = ao[2 * h + idx] + bo.f;                  \
                    float vc = ac[2 * h + idx] + bc.f;                  \
                    float ig = 1.0f / (1.0f + expf(-vi));               \
                    float og = 1.0f / (1.0f + expf(-vo));               \
                    float cc = (vc > 0.0f) ? vc : expm1f(vc);           \
                    float cell = oc.f + cc * ig;                        \
                    ncell.f = cell;                                     \
                    nh.f = tanhf(cell) * og;                            \
                }
                LANE(x, 0) LANE(y, 1)
#undef LANE
                *reinterpret_cast<float2*>(&out[row * SDIM + col]) = nh;
                *reinterpret_cast<float2*>(&out[HSIZE + row * SDIM + col]) = ncell;
            }
        }
    }
}

// ---------------- host ----------------
extern "C" void kernel_launch(void* const* d_in, const int* in_sizes, int n_in,
                              void* d_out, int out_size) {
    const float* W     = (const float*)d_in[0];   // (4096, 6144)
    const float* bias  = (const float*)d_in[1];   // (6144,)
    const float* input = (const float*)d_in[2];   // (4096, 2048)
    const float* old_h = (const float*)d_in[3];   // (4096, 2048)
    const float* old_c = (const float*)d_in[4];   // (4096, 2048)
    float* out = (float*)d_out;                   // [new_h | new_cell]

    void *pA0, *pA1, *pB0, *pB1;
    cudaGetSymbolAddress(&pA0, g_A0);
    cudaGetSymbolAddress(&pA1, g_A1);
    cudaGetSymbolAddress(&pB0, g_B0);
    cudaGetSymbolAddress(&pB1, g_B1);

    pack_split_x<<<16384, 256>>>(old_h, input, (__nv_bfloat16*)pA0, (__nv_bfloat16*)pA1);
    split_w_kernel<<<dim3(NGATE / 32, KDIM / 32), dim3(32, 8)>>>(
        W, (__nv_bfloat16*)pB0, (__nv_bfloat16*)pB1);

    cudaFuncSetAttribute(lltm_fused_kernel, cudaFuncAttributeMaxDynamicSharedMemorySize,
                         SMEM_TOTAL);
    lltm_fused_kernel<<<dim3(BDIM / BM, SDIM / BNS), NTHREADS, SMEM_TOTAL>>>(
        (const __nv_bfloat16*)pA0, (const __nv_bfloat16*)pA1,
        (const __nv_bfloat16*)pB0, (const __nv_bfloat16*)pB1, bias, old_c, out);
}

// round 8
// speedup vs baseline: 1.5622x; 1.0644x over previous
#include <cuda_runtime.h>
#include <cuda_bf16.h>
#include <cstdint>
#include <math.h>

// ---------------- problem constants ----------------
#define BDIM   4096          // batch rows
#define KDIM   4096          // F + S
#define NGATE  6144          // 3*S
#define SDIM   2048
#define HSIZE  8388608L      // B*S

// ---------------- tile config: shared-tile 3-product scheme ----------------
// Per k-chunk the stage holds A0,A1 (128x32) and B0,B1 (96x32). The 3 products
// A0B0 + A1B0 + A0B1 are computed from ONE load of each tile (33% less traffic
// than streaming 3 phases).
#define BM 128
#define BNS 32               // state-columns per CTA; B tile = 3 gates x 32 = 96 rows
#define BNROWS 96
#define BK 32                // 32 bf16 along k per chunk = 2 k16 slices
#define KT (KDIM / BK)       // 128 chunks total (single pass over K)
#define STAGES 2
#define NTHREADS 128

// smem: row stride 80 bytes (64 data + 16 pad) -> conflict-free ldmatrix/cp.async
#define ROWB 80
#define A_T (BM * ROWB)                   // 10240 per A tile
#define B_T (BNROWS * ROWB)               // 7680 per B tile
#define STAGE_BYTES (2 * A_T + 2 * B_T)   // 35840
#define SMEM_TOTAL (STAGES * STAGE_BYTES) // 71680 (x3 CTAs = 215KB/SM)

// ---------------- scratch (no cudaMalloc allowed) ----------------
__device__ __nv_bfloat16 g_A0[(long)BDIM * KDIM];    // 32MB  bf16(X)
__device__ __nv_bfloat16 g_A1[(long)BDIM * KDIM];    // 32MB  bf16(X - A0)
__device__ __nv_bfloat16 g_B0[(long)NGATE * KDIM];   // 50MB  bf16(W^T)
__device__ __nv_bfloat16 g_B1[(long)NGATE * KDIM];   // 50MB  bf16(W^T - B0)

// ---------------- helpers ----------------
__device__ __forceinline__ uint32_t smem_u32(const void* p) {
    uint32_t a;
    asm("{ .reg .u64 t; cvta.to.shared.u64 t, %1; cvt.u32.u64 %0, t; }" : "=r"(a) : "l"(p));
    return a;
}
__device__ __forceinline__ void cp16(uint32_t dst, const void* src) {
    asm volatile("cp.async.cg.shared.global [%0], [%1], 16;" :: "r"(dst), "l"(src) : "memory");
}
__device__ __forceinline__ void cp_commit() {
    asm volatile("cp.async.commit_group;" ::: "memory");
}
template <int N>
__device__ __forceinline__ void cp_wait() {
    asm volatile("cp.async.wait_group %0;" :: "n"(N) : "memory");
}
__device__ __forceinline__ void ldsm4(uint32_t& r0, uint32_t& r1, uint32_t& r2, uint32_t& r3,
                                      uint32_t addr) {
    asm volatile("ldmatrix.sync.aligned.m8n8.x4.shared.b16 {%0,%1,%2,%3}, [%4];"
                 : "=r"(r0), "=r"(r1), "=r"(r2), "=r"(r3) : "r"(addr));
}
__device__ __forceinline__ void mma_bf16(float* c, const uint32_t* a, const uint32_t* b) {
    asm volatile(
        "mma.sync.aligned.m16n8k16.row.col.f32.bf16.bf16.f32 "
        "{%0,%1,%2,%3}, {%4,%5,%6,%7}, {%8,%9}, {%0,%1,%2,%3};"
        : "+f"(c[0]), "+f"(c[1]), "+f"(c[2]), "+f"(c[3])
        : "r"(a[0]), "r"(a[1]), "r"(a[2]), "r"(a[3]), "r"(b[0]), "r"(b[1]));
}
__device__ __forceinline__ void split2(float x, __nv_bfloat16& h0, __nv_bfloat16& h1) {
    h0 = __float2bfloat16_rn(x);
    h1 = __float2bfloat16_rn(x - __bfloat162float(h0));
}

// ---------------- prologue: pack & split X = [old_h | input] ----------------
__global__ void pack_split_x(const float* __restrict__ old_h, const float* __restrict__ input,
                             __nv_bfloat16* __restrict__ A0, __nv_bfloat16* __restrict__ A1) {
    long i = (long)blockIdx.x * blockDim.x + threadIdx.x;   // float4 units, 4096*1024
    int m = (int)(i >> 10);
    int kq = (int)(i & 1023);
    float4 v = (kq < 512) ? reinterpret_cast<const float4*>(old_h)[(long)m * 512 + kq]
                          : reinterpret_cast<const float4*>(input)[(long)m * 512 + (kq - 512)];
    __nv_bfloat16 h0[4], h1[4];
    split2(v.x, h0[0], h1[0]);
    split2(v.y, h0[1], h1[1]);
    split2(v.z, h0[2], h1[2]);
    split2(v.w, h0[3], h1[3]);
    *reinterpret_cast<uint2*>(&A0[4 * i]) = *reinterpret_cast<uint2*>(h0);
    *reinterpret_cast<uint2*>(&A1[4 * i]) = *reinterpret_cast<uint2*>(h1);
}

// ---------------- prologue: transpose & split W -> Wt[n][k] ----------------
__global__ void split_w_kernel(const float* __restrict__ W,
                               __nv_bfloat16* __restrict__ B0, __nv_bfloat16* __restrict__ B1) {
    __shared__ float tile[32][33];
    int n0 = blockIdx.x * 32, k0 = blockIdx.y * 32;
    int tx = threadIdx.x, ty = threadIdx.y;
#pragma unroll
    for (int i = 0; i < 32; i += 8)
        tile[ty + i][tx] = W[(long)(k0 + ty + i) * NGATE + n0 + tx];
    __syncthreads();
#pragma unroll
    for (int i = 0; i < 32; i += 8) {
        long n = n0 + ty + i, k = k0 + tx;
        __nv_bfloat16 h0, h1;
        split2(tile[tx][ty + i], h0, h1);
        B0[n * KDIM + k] = h0;
        B1[n * KDIM + k] = h1;
    }
}

// ---------------- fused GEMM + LLTM epilogue (shared-tile 3-product) ----------------
// CTA: 128 rows x 32 state-cols x 3 gates. 4 warps 4(m)x1(n), warp tile 32x96.
__global__ void __launch_bounds__(NTHREADS, 3) lltm_fused_kernel(
    const __nv_bfloat16* __restrict__ A0, const __nv_bfloat16* __restrict__ A1,
    const __nv_bfloat16* __restrict__ B0, const __nv_bfloat16* __restrict__ B1,
    const float* __restrict__ bias, const float* __restrict__ old_c,
    float* __restrict__ out) {
    extern __shared__ char smem[];
    const uint32_t sbase = smem_u32(smem);

    const int tid = threadIdx.x;
    const int warp = tid >> 5, lane = tid & 31;
    const int g = lane >> 2, t4 = lane & 3;
    const long m0 = (long)blockIdx.x * BM;
    const int n0s = blockIdx.y * BNS;        // state-column base (0..2047)

    float acc[2][12][4];
#pragma unroll
    for (int i = 0; i < 2; i++)
#pragma unroll
        for (int j = 0; j < 12; j++)
#pragma unroll
            for (int r = 0; r < 4; r++) acc[i][j][r] = 0.0f;

    // per-lane ldmatrix offsets (within a tile)
    const uint32_t a_off = (uint32_t)(warp * 32 + (lane & 15)) * ROWB + ((lane >> 4) << 4);
    const uint32_t b_off =
        (uint32_t)((lane & 7) + ((lane >> 4) << 3)) * ROWB + (((lane >> 3) & 1) << 4);

    // stage loader: A0/A1 128 rows x 64B (4 chunks/thread each),
    //               B0/B1 96 rows x 64B (3 chunks/thread each)
    auto issue_stage = [&](int t) {
        int slot = t & (STAGES - 1);
        long kk = (long)t * BK;
        uint32_t sA0 = sbase + slot * STAGE_BYTES;
        uint32_t sA1 = sA0 + A_T;
        uint32_t sB0 = sA1 + A_T;
        uint32_t sB1 = sB0 + B_T;
#pragma unroll
        for (int i = 0; i < 4; i++) {
            int q = tid + i * NTHREADS;
            int row = q >> 2, cw = q & 3;
            long goff = (m0 + row) * KDIM + kk + cw * 8;
            cp16(sA0 + row * ROWB + cw * 16, A0 + goff);
            cp16(sA1 + row * ROWB + cw * 16, A1 + goff);
        }
#pragma unroll
        for (int i = 0; i < 3; i++) {
            int q = tid + i * NTHREADS;
            int row = q >> 2, cw = q & 3;        // row 0..95
            long grow = (long)(row >> 5) * SDIM + n0s + (row & 31);
            long goff = grow * KDIM + kk + cw * 8;
            cp16(sB0 + row * ROWB + cw * 16, B0 + goff);
            cp16(sB1 + row * ROWB + cw * 16, B1 + goff);
        }
    };

    issue_stage(0);
    cp_commit();

    for (int t = 0; t < KT; t++) {
        cp_wait<0>();
        __syncthreads();

        if (t + 1 < KT) issue_stage(t + 1);
        cp_commit();

        uint32_t sA0 = sbase + (t & (STAGES - 1)) * STAGE_BYTES;
        uint32_t sA1 = sA0 + A_T;
        uint32_t sB0 = sA1 + A_T;
        uint32_t sB1 = sB0 + B_T;

#pragma unroll
        for (int s = 0; s < 2; s++) {            // 2 k16 slices per chunk
            const uint32_t ks = (uint32_t)s * 32;
            uint32_t a0[2][4], a1[2][4], b[12][2];
#pragma unroll
            for (int i = 0; i < 2; i++) {
                ldsm4(a0[i][0], a0[i][1], a0[i][2], a0[i][3],
                      sA0 + a_off + (uint32_t)i * (16 * ROWB) + ks);
                ldsm4(a1[i][0], a1[i][1], a1[i][2], a1[i][3],
                      sA1 + a_off + (uint32_t)i * (16 * ROWB) + ks);
            }
            // product 1+2: (A0 + A1) x B0
#pragma unroll
            for (int jj = 0; jj < 6; jj++)
                ldsm4(b[2 * jj][0], b[2 * jj][1], b[2 * jj + 1][0], b[2 * jj + 1][1],
                      sB0 + b_off + (uint32_t)jj * (16 * ROWB) + ks);
#pragma unroll
            for (int i = 0; i < 2; i++)
#pragma unroll
                for (int j = 0; j < 12; j++) mma_bf16(acc[i][j], a0[i], b[j]);
#pragma unroll
            for (int i = 0; i < 2; i++)
#pragma unroll
                for (int j = 0; j < 12; j++) mma_bf16(acc[i][j], a1[i], b[j]);
            // product 3: A0 x B1 (reuse b registers)
#pragma unroll
            for (int jj = 0; jj < 6; jj++)
                ldsm4(b[2 * jj][0], b[2 * jj][1], b[2 * jj + 1][0], b[2 * jj + 1][1],
                      sB1 + b_off + (uint32_t)jj * (16 * ROWB) + ks);
#pragma unroll
            for (int i = 0; i < 2; i++)
#pragma unroll
                for (int j = 0; j < 12; j++) mma_bf16(acc[i][j], a0[i], b[j]);
        }
    }

    // ---- fused LLTM epilogue ----
#pragma unroll
    for (int i = 0; i < 2; i++) {
        long row0 = m0 + warp * 32 + i * 16 + g;
#pragma unroll
        for (int sj = 0; sj < 4; sj++) {
            int col = n0s + sj * 8 + 2 * t4;
            float2 bi = *reinterpret_cast<const float2*>(&bias[col]);
            float2 bo = *reinterpret_cast<const float2*>(&bias[SDIM + col]);
            float2 bc = *reinterpret_cast<const float2*>(&bias[2 * SDIM + col]);
            const float* ai = acc[i][sj];
            const float* ao = acc[i][sj + 4];
            const float* ac = acc[i][sj + 8];
#pragma unroll
            for (int h = 0; h < 2; h++) {        // h=0: row0, h=1: row0+8
                long row = row0 + 8 * h;
                float2 oc = *reinterpret_cast<const float2*>(&old_c[row * SDIM + col]);
                float2 nh, ncell;
#define LANE(f, idx)                                                    \
                {                                                       \
                    float vi = ai[2 * h + idx] + bi.f;                  \
                    float vo = ao[2 * h + idx] + bo.f;                  \
                    float vc = ac[2 * h + idx] + bc.f;                  \
                    float ig = 1.0f / (1.0f + expf(-vi));               \
                    float og = 1.0f / (1.0f + expf(-vo));               \
                    float cc = (vc > 0.0f) ? vc : expm1f(vc);           \
                    float cell = oc.f + cc * ig;                        \
                    ncell.f = cell;                                     \
                    nh.f = tanhf(cell) * og;                            \
                }
                LANE(x, 0) LANE(y, 1)
#undef LANE
                *reinterpret_cast<float2*>(&out[row * SDIM + col]) = nh;
                *reinterpret_cast<float2*>(&out[HSIZE + row * SDIM + col]) = ncell;
            }
        }
    }
}

// ---------------- host ----------------
extern "C" void kernel_launch(void* const* d_in, const int* in_sizes, int n_in,
                              void* d_out, int out_size) {
    const float* W     = (const float*)d_in[0];   // (4096, 6144)
    const float* bias  = (const float*)d_in[1];   // (6144,)
    const float* input = (const float*)d_in[2];   // (4096, 2048)
    const float* old_h = (const float*)d_in[3];   // (4096, 2048)
    const float* old_c = (const float*)d_in[4];   // (4096, 2048)
    float* out = (float*)d_out;                   // [new_h | new_cell]

    void *pA0, *pA1, *pB0, *pB1;
    cudaGetSymbolAddress(&pA0, g_A0);
    cudaGetSymbolAddress(&pA1, g_A1);
    cudaGetSymbolAddress(&pB0, g_B0);
    cudaGetSymbolAddress(&pB1, g_B1);

    pack_split_x<<<16384, 256>>>(old_h, input, (__nv_bfloat16*)pA0, (__nv_bfloat16*)pA1);
    split_w_kernel<<<dim3(NGATE / 32, KDIM / 32), dim3(32, 8)>>>(
        W, (__nv_bfloat16*)pB0, (__nv_bfloat16*)pB1);

    cudaFuncSetAttribute(lltm_fused_kernel, cudaFuncAttributeMaxDynamicSharedMemorySize,
                         SMEM_TOTAL);
    lltm_fused_kernel<<<dim3(BDIM / BM, SDIM / BNS), NTHREADS, SMEM_TOTAL>>>(
        (const __nv_bfloat16*)pA0, (const __nv_bfloat16*)pA1,
        (const __nv_bfloat16*)pB0, (const __nv_bfloat16*)pB1, bias, old_c, out);
}